// round 2
// baseline (speedup 1.0000x reference)
#include <cuda_runtime.h>
#include <math.h>

#define B_MAX 4096

typedef unsigned long long u64;

// Scratch (allocation-free): conv1 pooled output [B][16*14*14], dense angles [B][4]
__device__ float g_h1[B_MAX * 3136];
__device__ float g_ang[B_MAX * 4];

// ---------------------------------------------------------------------------
// f32x2 packed-FMA helpers (sm_103a: 2x FFMA throughput vs 3-reg FFMA)
// ---------------------------------------------------------------------------
__device__ __forceinline__ u64 pack2(float lo, float hi) {
    u64 r; asm("mov.b64 %0, {%1,%2};" : "=l"(r) : "f"(lo), "f"(hi)); return r;
}
__device__ __forceinline__ void unpack2(u64 v, float& lo, float& hi) {
    asm("mov.b64 {%0,%1}, %2;" : "=f"(lo), "=f"(hi) : "l"(v));
}
__device__ __forceinline__ u64 ffma2(u64 a, u64 b, u64 c) {
    u64 d; asm("fma.rn.f32x2 %0, %1, %2, %3;" : "=l"(d) : "l"(a), "l"(b), "l"(c));
    return d;
}
// (hi of a, lo of b) -> the kc=1 sliding pair
__device__ __forceinline__ u64 shpair(u64 a, u64 b) {
    return (a >> 32) | (b << 32);
}

// Apply one conv row tap-set (kr fixed, kc=0..2) to 7 packed accumulators.
// u[i] = packed input cols (2i, 2i+1); s[p] = packed cols (2p+1, 2p+2).
__device__ __forceinline__ void tap7(u64* a, const u64* u, const u64* s,
                                     const u64* wp, int kr) {
#pragma unroll
    for (int p = 0; p < 7; p++) a[p] = ffma2(u[p],     wp[kr * 3 + 0], a[p]);
#pragma unroll
    for (int p = 0; p < 7; p++) a[p] = ffma2(s[p],     wp[kr * 3 + 1], a[p]);
#pragma unroll
    for (int p = 0; p < 7; p++) a[p] = ffma2(u[p + 1], wp[kr * 3 + 2], a[p]);
}

// ---------------------------------------------------------------------------
// Kernel 1: conv1 (1->16, 3x3, pad 1) + ReLU + 2x2 maxpool. One image per CTA.
// 224 threads = 16 channels x 14 pooled rows; each thread does one pooled row
// in two 7-wide passes using packed f32x2 math.
// ---------------------------------------------------------------------------
__global__ __launch_bounds__(224) void k1_conv1(
    const float* __restrict__ x, const float* __restrict__ w,
    const float* __restrict__ b)
{
    __shared__ float sxp[30 * 32];   // zero-padded 30x30, row stride 32
    __shared__ float sw[144];
    __shared__ float sb[16];

    const int img = blockIdx.x;
    const int t = threadIdx.x;
    const float* xi = x + img * 784;

    for (int i = t; i < 960; i += 224) sxp[i] = 0.f;
    if (t < 144) sw[t] = w[t];
    if (t < 16)  sb[t] = b[t];
    __syncthreads();
    for (int i = t; i < 784; i += 224) {
        int r = i / 28, c = i % 28;
        sxp[(r + 1) * 32 + (c + 1)] = xi[i];
    }
    __syncthreads();

    const int ch = t / 14;   // 0..15
    const int pr = t % 14;   // pooled row 0..13

    u64 wp[9];
#pragma unroll
    for (int k = 0; k < 9; k++) { float wv = sw[ch * 9 + k]; wp[k] = pack2(wv, wv); }
    const float bb = sb[ch];
    const u64 bb2 = pack2(bb, bb);

    float* outp = g_h1 + (long)img * 3136 + ch * 196 + pr * 14;

#pragma unroll
    for (int pass = 0; pass < 2; pass++) {
        const int c0 = pass * 14;
        u64 acc[14];
#pragma unroll
        for (int i = 0; i < 14; i++) acc[i] = bb2;

#pragma unroll
        for (int j = 0; j < 4; j++) {
            const u64* rp = (const u64*)&sxp[(2 * pr + j) * 32 + c0];
            u64 u[8];
#pragma unroll
            for (int i = 0; i < 8; i++) u[i] = rp[i];
            u64 s[7];
#pragma unroll
            for (int p = 0; p < 7; p++) s[p] = shpair(u[p], u[p + 1]);

            if (j == 0) { tap7(acc, u, s, wp, 0); }
            else if (j == 1) { tap7(acc, u, s, wp, 1); tap7(acc + 7, u, s, wp, 0); }
            else if (j == 2) { tap7(acc, u, s, wp, 2); tap7(acc + 7, u, s, wp, 1); }
            else { tap7(acc + 7, u, s, wp, 2); }
        }

#pragma unroll
        for (int px = 0; px < 7; px++) {
            float a0, a1, b0, b1;
            unpack2(acc[px], a0, a1);
            unpack2(acc[7 + px], b0, b1);
            float m = fmaxf(fmaxf(fmaxf(a0, a1), fmaxf(b0, b1)), 0.f);
            outp[pass * 7 + px] = m;
        }
    }
}

// ---------------------------------------------------------------------------
// Kernel 2: conv2 (16->32, 3x3, pad 1) + ReLU + 2x2 maxpool + dense (1568->4).
// One image per CTA, 224 threads = 32 out-channels x 7 pooled rows.
// Packed f32x2 inner loop; input rows stride 18 (8B aligned + conflict-free).
// ---------------------------------------------------------------------------
#define K2_SIN   (16 * 288)            // 16 ch * 16 rows * 18 cols = 4608
#define K2_SW2   (32 * 145)            // 4640
#define K2_SDW   (4 * 1568)            // 6272
#define K2_FLOATS (K2_SIN + K2_SW2 + K2_SDW + 32 + 28)
#define K2_SMEM_BYTES (K2_FLOATS * 4)

__global__ __launch_bounds__(224) void k2_conv2_dense(
    const float* __restrict__ w2, const float* __restrict__ b2,
    const float* __restrict__ dw, const float* __restrict__ db)
{
    extern __shared__ float sm[];
    float* sin_ = sm;                      // [16][16*18] padded input
    float* sw2  = sm + K2_SIN;             // [32][145] (144 used)
    float* sdw  = sw2 + K2_SW2;            // [4][1568]
    float* sb2s = sdw + K2_SDW;            // [32]
    float* sred = sb2s + 32;               // [7][4]

    const int img = blockIdx.x;
    const int t = threadIdx.x;

    for (int i = t; i < K2_SIN; i += 224) sin_[i] = 0.f;
    __syncthreads();
    {
        const float* src = g_h1 + (long)img * 3136;
        for (int i = t; i < 3136; i += 224) {
            int ch = i / 196, p = i % 196;
            int r = p / 14, c = p % 14;
            sin_[ch * 288 + (r + 1) * 18 + (c + 1)] = src[i];
        }
    }
    for (int i = t; i < 4608; i += 224) {
        int ch = i / 144, rest = i % 144;
        sw2[ch * 145 + rest] = w2[i];
    }
    for (int i = t; i < 6272; i += 224) sdw[i] = dw[i];
    if (t < 32) sb2s[t] = b2[t];
    __syncthreads();

    const int ch = t / 7;   // output channel 0..31
    const int pr = t % 7;   // pooled row 0..6

    u64 acc[14];            // [o=0: pairs 0..6][o=1: pairs 7..13], bias pre-added
    {
        const float bb = sb2s[ch];
        const u64 bb2 = pack2(bb, bb);
#pragma unroll
        for (int i = 0; i < 14; i++) acc[i] = bb2;
    }

    const float* wbase = &sw2[ch * 145];
    const float* rbase0 = &sin_[(2 * pr) * 18];

    for (int ic = 0; ic < 16; ic++) {
        u64 wp[9];
#pragma unroll
        for (int k = 0; k < 9; k++) {
            float wv = wbase[ic * 9 + k];
            wp[k] = pack2(wv, wv);
        }
        const float* rb = rbase0 + ic * 288;
#pragma unroll
        for (int j = 0; j < 4; j++) {
            const u64* rp = (const u64*)(rb + j * 18);
            u64 u[8];
#pragma unroll
            for (int i = 0; i < 8; i++) u[i] = rp[i];
            u64 s[7];
#pragma unroll
            for (int p = 0; p < 7; p++) s[p] = shpair(u[p], u[p + 1]);

            if (j == 0) { tap7(acc, u, s, wp, 0); }
            else if (j == 1) { tap7(acc, u, s, wp, 1); tap7(acc + 7, u, s, wp, 0); }
            else if (j == 2) { tap7(acc, u, s, wp, 2); tap7(acc + 7, u, s, wp, 1); }
            else { tap7(acc + 7, u, s, wp, 2); }
        }
    }

    // pool + relu + dense partials
    float a4[4] = {0.f, 0.f, 0.f, 0.f};
#pragma unroll
    for (int px = 0; px < 7; px++) {
        float a0, a1, b0, b1;
        unpack2(acc[px], a0, a1);
        unpack2(acc[7 + px], b0, b1);
        float pooled = fmaxf(fmaxf(fmaxf(a0, a1), fmaxf(b0, b1)), 0.f);
        const int fi = ch * 49 + pr * 7 + px;
#pragma unroll
        for (int o = 0; o < 4; o++)
            a4[o] = fmaf(pooled, sdw[o * 1568 + fi], a4[o]);
    }

    // warp reduce (7 full warps)
#pragma unroll
    for (int o = 0; o < 4; o++)
#pragma unroll
        for (int off = 16; off > 0; off >>= 1)
            a4[o] += __shfl_down_sync(0xffffffffu, a4[o], off);
    const int lane = t & 31, wid = t >> 5;
    if (lane == 0) {
#pragma unroll
        for (int o = 0; o < 4; o++) sred[wid * 4 + o] = a4[o];
    }
    __syncthreads();
    if (t < 4) {
        float s = db[t];
#pragma unroll
        for (int w = 0; w < 7; w++) s += sred[w * 4 + t];
        g_ang[img * 4 + t] = s;
    }
}

// ---------------------------------------------------------------------------
// Kernel 3: 4-qubit statevector sim + post linear. One thread per image.
// ---------------------------------------------------------------------------
__device__ __forceinline__ float2 cmul(float2 a, float2 b) {
    return make_float2(fmaf(a.x, b.x, -a.y * b.y), fmaf(a.x, b.y, a.y * b.x));
}

__device__ __forceinline__ void ap1(float2* s, int bit,
                                    float2 m00, float2 m01, float2 m10, float2 m11)
{
#pragma unroll
    for (int i = 0; i < 16; i++) {
        if (!(i & bit)) {
            const int i1 = i | bit;
            float2 a0 = s[i], a1 = s[i1];
            float2 r0, r1;
            r0.x = m00.x * a0.x - m00.y * a0.y + m01.x * a1.x - m01.y * a1.y;
            r0.y = m00.x * a0.y + m00.y * a0.x + m01.x * a1.y + m01.y * a1.x;
            r1.x = m10.x * a0.x - m10.y * a0.y + m11.x * a1.x - m11.y * a1.y;
            r1.y = m10.x * a0.y + m10.y * a0.x + m11.x * a1.y + m11.y * a1.x;
            s[i] = r0; s[i1] = r1;
        }
    }
}

__global__ __launch_bounds__(128) void k3_quantum_post(
    const float* __restrict__ qp, const float* __restrict__ pw,
    const float* __restrict__ pb, float* __restrict__ out, int B)
{
    const int img = blockIdx.x * blockDim.x + threadIdx.x;
    if (img >= B) return;

    float2 s[16];
#pragma unroll
    for (int i = 0; i < 16; i++) s[i] = make_float2(0.f, 0.f);
    s[0] = make_float2(1.f, 0.f);

    // initial per-wire RY(pi*angle)
#pragma unroll
    for (int w = 0; w < 4; w++) {
        const float th = g_ang[img * 4 + w] * 3.14159265358979323846f * 0.5f;
        float sn, cs;
        sincosf(th, &sn, &cs);
        ap1(s, 8 >> w, make_float2(cs, 0.f), make_float2(-sn, 0.f),
            make_float2(sn, 0.f), make_float2(cs, 0.f));
    }

    const int pc_[6] = {0, 0, 0, 1, 1, 2};
    const int pt_[6] = {1, 2, 3, 2, 3, 3};

#pragma unroll
    for (int l = 0; l < 2; l++) {
        const int st = l * 18;
        // single-qubit rotations: M = RZ(g) RY(b) RX(a)
#pragma unroll
        for (int q = 0; q < 4; q++) {
            float a = qp[st + q * 3 + 0];
            float b = qp[st + q * 3 + 1];
            float g = qp[st + q * 3 + 2];
            float sa, ca, sb, cb, sg, cg;
            sincosf(a * 0.5f, &sa, &ca);
            sincosf(b * 0.5f, &sb, &cb);
            sincosf(g * 0.5f, &sg, &cg);
            // RY@RX
            float2 m00 = make_float2(cb * ca,  sb * sa);
            float2 m01 = make_float2(-sb * ca, -cb * sa);
            float2 m10 = make_float2(sb * ca,  -cb * sa);
            float2 m11 = make_float2(cb * ca,  -sb * sa);
            const float2 em = make_float2(cg, -sg);  // e^{-i g/2}
            const float2 ep = make_float2(cg,  sg);  // e^{+i g/2}
            m00 = cmul(em, m00); m01 = cmul(em, m01);
            m10 = cmul(ep, m10); m11 = cmul(ep, m11);
            ap1(s, 8 >> q, m00, m01, m10, m11);
        }
        // entanglers: M4 = kron(I, RZ(phi)) @ CNOT
#pragma unroll
        for (int k = 0; k < 6; k++) {
            const float phi = qp[st + 12 + k] * 0.5f;
            float sp, cp;
            sincosf(phi, &sp, &cp);
            const float2 em = make_float2(cp, -sp);
            const float2 ep = make_float2(cp,  sp);
            const int bc = 8 >> pc_[k];
            const int bt = 8 >> pt_[k];
#pragma unroll
            for (int base = 0; base < 16; base++) {
                if (!(base & (bc | bt))) {
                    const int i01 = base | bt, i10 = base | bc, i11 = base | bc | bt;
                    float2 t00 = s[base], t01 = s[i01], t10 = s[i10], t11 = s[i11];
                    s[base] = cmul(em, t00);
                    s[i01]  = cmul(ep, t01);
                    s[i10]  = cmul(em, t11);
                    s[i11]  = cmul(ep, t10);
                }
            }
        }
    }

    // Z expectations
    float z[4];
#pragma unroll
    for (int w = 0; w < 4; w++) {
        const int bit = 8 >> w;
        float zv = 0.f;
#pragma unroll
        for (int i = 0; i < 16; i++) {
            const float p = s[i].x * s[i].x + s[i].y * s[i].y;
            zv += (i & bit) ? -p : p;
        }
        z[w] = zv;
    }

    // post linear (4 -> 10)
#pragma unroll
    for (int k = 0; k < 10; k++) {
        float o = pb[k];
#pragma unroll
        for (int j = 0; j < 4; j++) o = fmaf(z[j], pw[k * 4 + j], o);
        out[img * 10 + k] = o;
    }
}

// ---------------------------------------------------------------------------
extern "C" void kernel_launch(void* const* d_in, const int* in_sizes, int n_in,
                              void* d_out, int out_size)
{
    const float* x    = (const float*)d_in[0];
    const float* c1w  = (const float*)d_in[1];
    const float* c1b  = (const float*)d_in[2];
    const float* c2w  = (const float*)d_in[3];
    const float* c2b  = (const float*)d_in[4];
    const float* dw   = (const float*)d_in[5];
    const float* db   = (const float*)d_in[6];
    const float* qp   = (const float*)d_in[7];
    const float* pw   = (const float*)d_in[8];
    const float* pb   = (const float*)d_in[9];
    float* out = (float*)d_out;

    int B = in_sizes[0] / 784;
    if (B > B_MAX) B = B_MAX;

    cudaFuncSetAttribute(k2_conv2_dense,
                         cudaFuncAttributeMaxDynamicSharedMemorySize,
                         K2_SMEM_BYTES);

    k1_conv1<<<B, 224>>>(x, c1w, c1b);
    k2_conv2_dense<<<B, 224, K2_SMEM_BYTES>>>(c2w, c2b, dw, db);
    k3_quantum_post<<<(B + 127) / 128, 128>>>(qp, pw, pb, out, B);
}

// round 3
// speedup vs baseline: 1.1958x; 1.1958x over previous
#include <cuda_runtime.h>
#include <math.h>

#define B_MAX 4096

typedef unsigned long long u64;

// Scratch (allocation-free): conv1 pooled output [B][16*14*14], dense angles [B][4]
__device__ float g_h1[B_MAX * 3136];
__device__ float g_ang[B_MAX * 4];

// ---------------------------------------------------------------------------
// f32x2 packed-FMA helpers (sm_103a: 2x FFMA throughput vs 3-reg FFMA)
// ---------------------------------------------------------------------------
__device__ __forceinline__ u64 pack2(float lo, float hi) {
    u64 r; asm("mov.b64 %0, {%1,%2};" : "=l"(r) : "f"(lo), "f"(hi)); return r;
}
__device__ __forceinline__ void unpack2(u64 v, float& lo, float& hi) {
    asm("mov.b64 {%0,%1}, %2;" : "=f"(lo), "=f"(hi) : "l"(v));
}
__device__ __forceinline__ u64 ffma2(u64 a, u64 b, u64 c) {
    u64 d; asm("fma.rn.f32x2 %0, %1, %2, %3;" : "=l"(d) : "l"(a), "l"(b), "l"(c));
    return d;
}
// (hi of a, lo of b) -> the kc=1 sliding pair
__device__ __forceinline__ u64 shpair(u64 a, u64 b) {
    return (a >> 32) | (b << 32);
}

// Apply one conv row tap-set (kr fixed, kc=0..2) to 7 packed accumulators.
__device__ __forceinline__ void tap7(u64* a, const u64* u, const u64* s,
                                     const u64* wp, int kr) {
#pragma unroll
    for (int p = 0; p < 7; p++) a[p] = ffma2(u[p],     wp[kr * 3 + 0], a[p]);
#pragma unroll
    for (int p = 0; p < 7; p++) a[p] = ffma2(s[p],     wp[kr * 3 + 1], a[p]);
#pragma unroll
    for (int p = 0; p < 7; p++) a[p] = ffma2(u[p + 1], wp[kr * 3 + 2], a[p]);
}

// ---------------------------------------------------------------------------
// Kernel 1: conv1 (1->16, 3x3, pad 1) + ReLU + 2x2 maxpool. One image per CTA.
// 224 threads; WARP-FRIENDLY MAP: pr = t>>4 (2 per warp), ch = t&15.
// Input loads broadcast within warp; tile row stride 34 -> the two pr groups
// in a warp are 4 banks apart (conflict-free).
// ---------------------------------------------------------------------------
#define K1_STRIDE 34

__global__ __launch_bounds__(224) void k1_conv1(
    const float* __restrict__ x, const float* __restrict__ w,
    const float* __restrict__ b)
{
    __shared__ float sxp[30 * K1_STRIDE];   // zero-padded 30x30
    __shared__ float sw[144];
    __shared__ float sb[16];

    const int img = blockIdx.x;
    const int t = threadIdx.x;
    const float* xi = x + img * 784;

    for (int i = t; i < 30 * K1_STRIDE; i += 224) sxp[i] = 0.f;
    if (t < 144) sw[t] = w[t];
    if (t < 16)  sb[t] = b[t];
    __syncthreads();
    for (int i = t; i < 784; i += 224) {
        int r = i / 28, c = i % 28;
        sxp[(r + 1) * K1_STRIDE + (c + 1)] = xi[i];
    }
    __syncthreads();

    const int pr = t >> 4;   // pooled row 0..13 (2 per warp)
    const int ch = t & 15;   // channel 0..15

    u64 wp[9];
#pragma unroll
    for (int k = 0; k < 9; k++) { float wv = sw[ch * 9 + k]; wp[k] = pack2(wv, wv); }
    const float bb = sb[ch];
    const u64 bb2 = pack2(bb, bb);

    float* outp = g_h1 + (long)img * 3136 + ch * 196 + pr * 14;

#pragma unroll
    for (int pass = 0; pass < 2; pass++) {
        const int c0 = pass * 14;
        u64 acc[14];
#pragma unroll
        for (int i = 0; i < 14; i++) acc[i] = bb2;

#pragma unroll
        for (int j = 0; j < 4; j++) {
            const u64* rp = (const u64*)&sxp[(2 * pr + j) * K1_STRIDE + c0];
            u64 u[8];
#pragma unroll
            for (int i = 0; i < 8; i++) u[i] = rp[i];
            u64 s[7];
#pragma unroll
            for (int p = 0; p < 7; p++) s[p] = shpair(u[p], u[p + 1]);

            if (j == 0) { tap7(acc, u, s, wp, 0); }
            else if (j == 1) { tap7(acc, u, s, wp, 1); tap7(acc + 7, u, s, wp, 0); }
            else if (j == 2) { tap7(acc, u, s, wp, 2); tap7(acc + 7, u, s, wp, 1); }
            else { tap7(acc + 7, u, s, wp, 2); }
        }

#pragma unroll
        for (int px = 0; px < 7; px++) {
            float a0, a1, b0, b1;
            unpack2(acc[px], a0, a1);
            unpack2(acc[7 + px], b0, b1);
            float m = fmaxf(fmaxf(fmaxf(a0, a1), fmaxf(b0, b1)), 0.f);
            outp[pass * 7 + px] = m;
        }
    }
}

// ---------------------------------------------------------------------------
// Kernel 2: conv2 (16->32, 3x3, pad 1) + ReLU + 2x2 maxpool + dense (1568->4).
// One image per CTA, 224 threads; WARP-FRIENDLY MAP: pr = t>>5, ch = t&31.
// Each warp = one pooled row x 32 channels: input LDS are pure broadcasts,
// weight LDS lane-stride 145 == 17 mod 32 (conflict-free), dense stride 49
// == 17 mod 32 (conflict-free). Packed f32x2 inner loop.
// ---------------------------------------------------------------------------
#define K2_SIN   (16 * 288)            // 16 ch * 16 rows * 18 cols = 4608
#define K2_SW2   (32 * 145)            // 4640
#define K2_SDW   (4 * 1568)            // 6272
#define K2_FLOATS (K2_SIN + K2_SW2 + K2_SDW + 32 + 28)
#define K2_SMEM_BYTES (K2_FLOATS * 4)

__global__ __launch_bounds__(224) void k2_conv2_dense(
    const float* __restrict__ w2, const float* __restrict__ b2,
    const float* __restrict__ dw, const float* __restrict__ db)
{
    extern __shared__ float sm[];
    float* sin_ = sm;                      // [16][16*18] padded input
    float* sw2  = sm + K2_SIN;             // [32][145] (144 used)
    float* sdw  = sw2 + K2_SW2;            // [4][1568]
    float* sb2s = sdw + K2_SDW;            // [32]
    float* sred = sb2s + 32;               // [7][4]

    const int img = blockIdx.x;
    const int t = threadIdx.x;

    for (int i = t; i < K2_SIN; i += 224) sin_[i] = 0.f;
    __syncthreads();
    {
        const float* src = g_h1 + (long)img * 3136;
        for (int i = t; i < 3136; i += 224) {
            int ch = i / 196, p = i % 196;
            int r = p / 14, c = p % 14;
            sin_[ch * 288 + (r + 1) * 18 + (c + 1)] = src[i];
        }
    }
    for (int i = t; i < 4608; i += 224) {
        int ch = i / 144, rest = i % 144;
        sw2[ch * 145 + rest] = w2[i];
    }
    for (int i = t; i < 6272; i += 224) sdw[i] = dw[i];
    if (t < 32) sb2s[t] = b2[t];
    __syncthreads();

    const int pr = t >> 5;   // pooled row 0..6 (one per warp)
    const int ch = t & 31;   // output channel 0..31

    u64 acc[14];             // [o=0: pairs 0..6][o=1: pairs 7..13]
    {
        const float bb = sb2s[ch];
        const u64 bb2 = pack2(bb, bb);
#pragma unroll
        for (int i = 0; i < 14; i++) acc[i] = bb2;
    }

    const float* wbase = &sw2[ch * 145];
    const float* rbase0 = &sin_[(2 * pr) * 18];

    for (int ic = 0; ic < 16; ic++) {
        u64 wp[9];
#pragma unroll
        for (int k = 0; k < 9; k++) {
            float wv = wbase[ic * 9 + k];
            wp[k] = pack2(wv, wv);
        }
        const float* rb = rbase0 + ic * 288;
#pragma unroll
        for (int j = 0; j < 4; j++) {
            const u64* rp = (const u64*)(rb + j * 18);
            u64 u[8];
#pragma unroll
            for (int i = 0; i < 8; i++) u[i] = rp[i];
            u64 s[7];
#pragma unroll
            for (int p = 0; p < 7; p++) s[p] = shpair(u[p], u[p + 1]);

            if (j == 0) { tap7(acc, u, s, wp, 0); }
            else if (j == 1) { tap7(acc, u, s, wp, 1); tap7(acc + 7, u, s, wp, 0); }
            else if (j == 2) { tap7(acc, u, s, wp, 2); tap7(acc + 7, u, s, wp, 1); }
            else { tap7(acc + 7, u, s, wp, 2); }
        }
    }

    // pool + relu + dense partials
    float a4[4] = {0.f, 0.f, 0.f, 0.f};
#pragma unroll
    for (int px = 0; px < 7; px++) {
        float a0, a1, b0, b1;
        unpack2(acc[px], a0, a1);
        unpack2(acc[7 + px], b0, b1);
        float pooled = fmaxf(fmaxf(fmaxf(a0, a1), fmaxf(b0, b1)), 0.f);
        const int fi = ch * 49 + pr * 7 + px;
#pragma unroll
        for (int o = 0; o < 4; o++)
            a4[o] = fmaf(pooled, sdw[o * 1568 + fi], a4[o]);
    }

    // warp reduce (each warp = one pr, reduce over ch)
#pragma unroll
    for (int o = 0; o < 4; o++)
#pragma unroll
        for (int off = 16; off > 0; off >>= 1)
            a4[o] += __shfl_down_sync(0xffffffffu, a4[o], off);
    const int lane = t & 31, wid = t >> 5;
    if (lane == 0) {
#pragma unroll
        for (int o = 0; o < 4; o++) sred[wid * 4 + o] = a4[o];
    }
    __syncthreads();
    if (t < 4) {
        float s = db[t];
#pragma unroll
        for (int w = 0; w < 7; w++) s += sred[w * 4 + t];
        g_ang[img * 4 + t] = s;
    }
}

// ---------------------------------------------------------------------------
// Kernel 3: 4-qubit statevector sim + post linear. One thread per image.
// ---------------------------------------------------------------------------
__device__ __forceinline__ float2 cmul(float2 a, float2 b) {
    return make_float2(fmaf(a.x, b.x, -a.y * b.y), fmaf(a.x, b.y, a.y * b.x));
}

__device__ __forceinline__ void ap1(float2* s, int bit,
                                    float2 m00, float2 m01, float2 m10, float2 m11)
{
#pragma unroll
    for (int i = 0; i < 16; i++) {
        if (!(i & bit)) {
            const int i1 = i | bit;
            float2 a0 = s[i], a1 = s[i1];
            float2 r0, r1;
            r0.x = m00.x * a0.x - m00.y * a0.y + m01.x * a1.x - m01.y * a1.y;
            r0.y = m00.x * a0.y + m00.y * a0.x + m01.x * a1.y + m01.y * a1.x;
            r1.x = m10.x * a0.x - m10.y * a0.y + m11.x * a1.x - m11.y * a1.y;
            r1.y = m10.x * a0.y + m10.y * a0.x + m11.x * a1.y + m11.y * a1.x;
            s[i] = r0; s[i1] = r1;
        }
    }
}

__global__ __launch_bounds__(128) void k3_quantum_post(
    const float* __restrict__ qp, const float* __restrict__ pw,
    const float* __restrict__ pb, float* __restrict__ out, int B)
{
    const int img = blockIdx.x * blockDim.x + threadIdx.x;
    if (img >= B) return;

    float2 s[16];
#pragma unroll
    for (int i = 0; i < 16; i++) s[i] = make_float2(0.f, 0.f);
    s[0] = make_float2(1.f, 0.f);

    // initial per-wire RY(pi*angle)
#pragma unroll
    for (int w = 0; w < 4; w++) {
        const float th = g_ang[img * 4 + w] * 3.14159265358979323846f * 0.5f;
        float sn, cs;
        sincosf(th, &sn, &cs);
        ap1(s, 8 >> w, make_float2(cs, 0.f), make_float2(-sn, 0.f),
            make_float2(sn, 0.f), make_float2(cs, 0.f));
    }

    const int pc_[6] = {0, 0, 0, 1, 1, 2};
    const int pt_[6] = {1, 2, 3, 2, 3, 3};

#pragma unroll
    for (int l = 0; l < 2; l++) {
        const int st = l * 18;
#pragma unroll
        for (int q = 0; q < 4; q++) {
            float a = qp[st + q * 3 + 0];
            float b = qp[st + q * 3 + 1];
            float g = qp[st + q * 3 + 2];
            float sa, ca, sb, cb, sg, cg;
            sincosf(a * 0.5f, &sa, &ca);
            sincosf(b * 0.5f, &sb, &cb);
            sincosf(g * 0.5f, &sg, &cg);
            float2 m00 = make_float2(cb * ca,  sb * sa);
            float2 m01 = make_float2(-sb * ca, -cb * sa);
            float2 m10 = make_float2(sb * ca,  -cb * sa);
            float2 m11 = make_float2(cb * ca,  -sb * sa);
            const float2 em = make_float2(cg, -sg);
            const float2 ep = make_float2(cg,  sg);
            m00 = cmul(em, m00); m01 = cmul(em, m01);
            m10 = cmul(ep, m10); m11 = cmul(ep, m11);
            ap1(s, 8 >> q, m00, m01, m10, m11);
        }
#pragma unroll
        for (int k = 0; k < 6; k++) {
            const float phi = qp[st + 12 + k] * 0.5f;
            float sp, cp;
            sincosf(phi, &sp, &cp);
            const float2 em = make_float2(cp, -sp);
            const float2 ep = make_float2(cp,  sp);
            const int bc = 8 >> pc_[k];
            const int bt = 8 >> pt_[k];
#pragma unroll
            for (int base = 0; base < 16; base++) {
                if (!(base & (bc | bt))) {
                    const int i01 = base | bt, i10 = base | bc, i11 = base | bc | bt;
                    float2 t00 = s[base], t01 = s[i01], t10 = s[i10], t11 = s[i11];
                    s[base] = cmul(em, t00);
                    s[i01]  = cmul(ep, t01);
                    s[i10]  = cmul(em, t11);
                    s[i11]  = cmul(ep, t10);
                }
            }
        }
    }

    float z[4];
#pragma unroll
    for (int w = 0; w < 4; w++) {
        const int bit = 8 >> w;
        float zv = 0.f;
#pragma unroll
        for (int i = 0; i < 16; i++) {
            const float p = s[i].x * s[i].x + s[i].y * s[i].y;
            zv += (i & bit) ? -p : p;
        }
        z[w] = zv;
    }

#pragma unroll
    for (int k = 0; k < 10; k++) {
        float o = pb[k];
#pragma unroll
        for (int j = 0; j < 4; j++) o = fmaf(z[j], pw[k * 4 + j], o);
        out[img * 10 + k] = o;
    }
}

// ---------------------------------------------------------------------------
extern "C" void kernel_launch(void* const* d_in, const int* in_sizes, int n_in,
                              void* d_out, int out_size)
{
    const float* x    = (const float*)d_in[0];
    const float* c1w  = (const float*)d_in[1];
    const float* c1b  = (const float*)d_in[2];
    const float* c2w  = (const float*)d_in[3];
    const float* c2b  = (const float*)d_in[4];
    const float* dw   = (const float*)d_in[5];
    const float* db   = (const float*)d_in[6];
    const float* qp   = (const float*)d_in[7];
    const float* pw   = (const float*)d_in[8];
    const float* pb   = (const float*)d_in[9];
    float* out = (float*)d_out;

    int B = in_sizes[0] / 784;
    if (B > B_MAX) B = B_MAX;

    cudaFuncSetAttribute(k2_conv2_dense,
                         cudaFuncAttributeMaxDynamicSharedMemorySize,
                         K2_SMEM_BYTES);

    k1_conv1<<<B, 224>>>(x, c1w, c1b);
    k2_conv2_dense<<<B, 224, K2_SMEM_BYTES>>>(c2w, c2b, dw, db);
    k3_quantum_post<<<(B + 127) / 128, 128>>>(qp, pw, pb, out, B);
}

// round 4
// speedup vs baseline: 1.4721x; 1.2311x over previous
#include <cuda_runtime.h>
#include <math.h>

#define B_MAX 4096

typedef unsigned long long u64;

// Scratch: conv1 pooled output in k2-ready padded layout [B][16ch][16][16]
// (row/col 0 and 15 are zero borders), plus dense angles [B][4].
__device__ float g_h1[B_MAX * 4096];
__device__ float g_ang[B_MAX * 4];

// ---------------------------------------------------------------------------
// f32x2 packed-FMA helpers
// ---------------------------------------------------------------------------
__device__ __forceinline__ u64 pack2(float lo, float hi) {
    u64 r; asm("mov.b64 %0, {%1,%2};" : "=l"(r) : "f"(lo), "f"(hi)); return r;
}
__device__ __forceinline__ void unpack2(u64 v, float& lo, float& hi) {
    asm("mov.b64 {%0,%1}, %2;" : "=f"(lo), "=f"(hi) : "l"(v));
}
__device__ __forceinline__ u64 ffma2(u64 a, u64 b, u64 c) {
    u64 d; asm("fma.rn.f32x2 %0, %1, %2, %3;" : "=l"(d) : "l"(a), "l"(b), "l"(c));
    return d;
}
__device__ __forceinline__ u64 shpair(u64 a, u64 b) {
    return (a >> 32) | (b << 32);
}

__device__ __forceinline__ void tap7(u64* a, const u64* u, const u64* s,
                                     const u64* wp, int kr) {
#pragma unroll
    for (int p = 0; p < 7; p++) a[p] = ffma2(u[p],     wp[kr * 3 + 0], a[p]);
#pragma unroll
    for (int p = 0; p < 7; p++) a[p] = ffma2(s[p],     wp[kr * 3 + 1], a[p]);
#pragma unroll
    for (int p = 0; p < 7; p++) a[p] = ffma2(u[p + 1], wp[kr * 3 + 2], a[p]);
}

// ---------------------------------------------------------------------------
// Kernel 1: conv1 (1->16) + ReLU + 2x2 pool. One image per CTA, 196 threads,
// thread = one pooled position; 4x4 patch in registers reused across all 16
// channels; channels done in f32x2 pairs (cg, cg+8) with weights pre-packed.
// Output written in k2's padded [ch][16][16] layout (borders zeroed here).
// ---------------------------------------------------------------------------
#define K1S 34

__global__ __launch_bounds__(196, 4) void k1_conv1(
    const float* __restrict__ x, const float* __restrict__ w,
    const float* __restrict__ b)
{
    __shared__ float sxp[30 * K1S];   // zero-padded 30x30 input
    __shared__ u64 swp[80];           // [8 cg][9] packed weights + [8] packed bias

    const int img = blockIdx.x;
    const int t = threadIdx.x;
    const float* xi = x + img * 784;

    for (int i = t; i < 30 * K1S; i += 196) sxp[i] = 0.f;
    if (t < 72)      swp[t] = pack2(w[t], w[t + 72]);          // cg=t/9,k=t%9
    else if (t < 80) swp[t] = pack2(b[t - 72], b[t - 64]);
    __syncthreads();
#pragma unroll
    for (int k = 0; k < 4; k++) {                 // 784 = 4*196 exactly
        int i = t + k * 196;
        int r = i / 28, c = i % 28;
        sxp[(r + 1) * K1S + (c + 1)] = xi[i];
    }
    __syncthreads();

    const int pr = t / 14;
    const int pc = t % 14;

    // 4x4 patch -> packed (v,v)
    u64 pv[16];
    {
        const float* p0 = &sxp[(2 * pr) * K1S + 2 * pc];
#pragma unroll
        for (int j = 0; j < 4; j++) {
            float2 a = *(const float2*)(p0 + j * K1S);
            float2 bq = *(const float2*)(p0 + j * K1S + 2);
            pv[j * 4 + 0] = pack2(a.x, a.x);
            pv[j * 4 + 1] = pack2(a.y, a.y);
            pv[j * 4 + 2] = pack2(bq.x, bq.x);
            pv[j * 4 + 3] = pack2(bq.y, bq.y);
        }
    }

    float* outp = g_h1 + (long)img * 4096 + (pr + 1) * 16 + (pc + 1);

#pragma unroll
    for (int cg = 0; cg < 8; cg++) {
        u64 wp[9];
#pragma unroll
        for (int k = 0; k < 9; k++) wp[k] = swp[cg * 9 + k];
        const u64 bb = swp[72 + cg];
        u64 acc[4] = {bb, bb, bb, bb};
#pragma unroll
        for (int kr = 0; kr < 3; kr++)
#pragma unroll
            for (int kc = 0; kc < 3; kc++) {
                const u64 wv = wp[kr * 3 + kc];
#pragma unroll
                for (int dr = 0; dr < 2; dr++)
#pragma unroll
                    for (int dc = 0; dc < 2; dc++)
                        acc[dr * 2 + dc] =
                            ffma2(pv[(dr + kr) * 4 + (dc + kc)], wv, acc[dr * 2 + dc]);
            }
        float l0, h0, l1, h1, l2, h2, l3, h3;
        unpack2(acc[0], l0, h0); unpack2(acc[1], l1, h1);
        unpack2(acc[2], l2, h2); unpack2(acc[3], l3, h3);
        float mlo = fmaxf(fmaxf(fmaxf(l0, l1), fmaxf(l2, l3)), 0.f);
        float mhi = fmaxf(fmaxf(fmaxf(h0, h1), fmaxf(h2, h3)), 0.f);
        outp[cg * 256]       = mlo;
        outp[(cg + 8) * 256] = mhi;
    }

    // zero the 60 border cells per channel (disjoint from data cells)
    for (int i = t; i < 960; i += 196) {
        int ch = i / 60, j = i % 60;
        int r, c;
        if (j < 16)      { r = 0;  c = j; }
        else if (j < 32) { r = 15; c = j - 16; }
        else if (j < 46) { r = j - 31; c = 0; }
        else             { r = j - 45; c = 15; }
        g_h1[(long)img * 4096 + ch * 256 + r * 16 + c] = 0.f;
    }
}

// ---------------------------------------------------------------------------
// Kernel 2: conv2 (16->32) + ReLU + 2x2 pool + dense (1568->4).
// One image per CTA, 224 threads; warp = one pooled row x 32 channels.
// Static smem ~35KB -> 4 CTAs/SM (28 warps). Dense weights via __ldg (L2-hot).
// ---------------------------------------------------------------------------
__global__ __launch_bounds__(224, 4) void k2_conv2_dense(
    const float* __restrict__ w2, const float* __restrict__ b2,
    const float* __restrict__ dw, const float* __restrict__ db)
{
    __shared__ float sin_[16 * 256];   // [16ch][16][16] padded input (copied)
    __shared__ float sw2[32 * 145];    // weights, stride 145 (odd mod 32)
    __shared__ float sb2s[32];
    __shared__ float sred[28];

    const int img = blockIdx.x;
    const int t = threadIdx.x;

    {   // straight coalesced copy of padded image (4096 floats)
        const u64* src = (const u64*)(g_h1 + (long)img * 4096);
        u64* dst = (u64*)sin_;
        for (int i = t; i < 2048; i += 224) dst[i] = src[i];
    }
    for (int i = t; i < 4608; i += 224) {
        int ch = i / 144, rest = i % 144;
        sw2[ch * 145 + rest] = w2[i];
    }
    if (t < 32) sb2s[t] = b2[t];
    __syncthreads();

    const int pr = t >> 5;   // pooled row 0..6 (one per warp)
    const int ch = t & 31;   // output channel

    u64 acc[14];
    {
        const float bb = sb2s[ch];
        const u64 bb2 = pack2(bb, bb);
#pragma unroll
        for (int i = 0; i < 14; i++) acc[i] = bb2;
    }

    const float* wbase = &sw2[ch * 145];
    const float* rbase0 = &sin_[(2 * pr) * 16];

    for (int ic = 0; ic < 16; ic++) {
        u64 wp[9];
#pragma unroll
        for (int k = 0; k < 9; k++) {
            float wv = wbase[ic * 9 + k];
            wp[k] = pack2(wv, wv);
        }
        const float* rb = rbase0 + ic * 256;
#pragma unroll
        for (int j = 0; j < 4; j++) {
            const u64* rp = (const u64*)(rb + j * 16);
            u64 u[8];
#pragma unroll
            for (int i = 0; i < 8; i++) u[i] = rp[i];
            u64 s[7];
#pragma unroll
            for (int p = 0; p < 7; p++) s[p] = shpair(u[p], u[p + 1]);

            if (j == 0) { tap7(acc, u, s, wp, 0); }
            else if (j == 1) { tap7(acc, u, s, wp, 1); tap7(acc + 7, u, s, wp, 0); }
            else if (j == 2) { tap7(acc, u, s, wp, 2); tap7(acc + 7, u, s, wp, 1); }
            else { tap7(acc + 7, u, s, wp, 2); }
        }
    }

    // pool + relu + dense partials (dense weights from global; L2-hot)
    float a4[4] = {0.f, 0.f, 0.f, 0.f};
#pragma unroll
    for (int px = 0; px < 7; px++) {
        float a0, a1, b0, b1;
        unpack2(acc[px], a0, a1);
        unpack2(acc[7 + px], b0, b1);
        float pooled = fmaxf(fmaxf(fmaxf(a0, a1), fmaxf(b0, b1)), 0.f);
        const int fi = ch * 49 + pr * 7 + px;
#pragma unroll
        for (int o = 0; o < 4; o++)
            a4[o] = fmaf(pooled, __ldg(&dw[o * 1568 + fi]), a4[o]);
    }

#pragma unroll
    for (int o = 0; o < 4; o++)
#pragma unroll
        for (int off = 16; off > 0; off >>= 1)
            a4[o] += __shfl_down_sync(0xffffffffu, a4[o], off);
    const int lane = t & 31, wid = t >> 5;
    if (lane == 0) {
#pragma unroll
        for (int o = 0; o < 4; o++) sred[wid * 4 + o] = a4[o];
    }
    __syncthreads();
    if (t < 4) {
        float s = db[t];
#pragma unroll
        for (int w = 0; w < 7; w++) s += sred[w * 4 + t];
        g_ang[img * 4 + t] = s;
    }
}

// ---------------------------------------------------------------------------
// Kernel 3: 4-qubit statevector sim + post linear. One thread per image.
// ---------------------------------------------------------------------------
__device__ __forceinline__ float2 cmul(float2 a, float2 b) {
    return make_float2(fmaf(a.x, b.x, -a.y * b.y), fmaf(a.x, b.y, a.y * b.x));
}

__device__ __forceinline__ void ap1(float2* s, int bit,
                                    float2 m00, float2 m01, float2 m10, float2 m11)
{
#pragma unroll
    for (int i = 0; i < 16; i++) {
        if (!(i & bit)) {
            const int i1 = i | bit;
            float2 a0 = s[i], a1 = s[i1];
            float2 r0, r1;
            r0.x = m00.x * a0.x - m00.y * a0.y + m01.x * a1.x - m01.y * a1.y;
            r0.y = m00.x * a0.y + m00.y * a0.x + m01.x * a1.y + m01.y * a1.x;
            r1.x = m10.x * a0.x - m10.y * a0.y + m11.x * a1.x - m11.y * a1.y;
            r1.y = m10.x * a0.y + m10.y * a0.x + m11.x * a1.y + m11.y * a1.x;
            s[i] = r0; s[i1] = r1;
        }
    }
}

__global__ __launch_bounds__(128) void k3_quantum_post(
    const float* __restrict__ qp, const float* __restrict__ pw,
    const float* __restrict__ pb, float* __restrict__ out, int B)
{
    const int img = blockIdx.x * blockDim.x + threadIdx.x;
    if (img >= B) return;

    float2 s[16];
#pragma unroll
    for (int i = 0; i < 16; i++) s[i] = make_float2(0.f, 0.f);
    s[0] = make_float2(1.f, 0.f);

#pragma unroll
    for (int w = 0; w < 4; w++) {
        const float th = g_ang[img * 4 + w] * 3.14159265358979323846f * 0.5f;
        float sn, cs;
        sincosf(th, &sn, &cs);
        ap1(s, 8 >> w, make_float2(cs, 0.f), make_float2(-sn, 0.f),
            make_float2(sn, 0.f), make_float2(cs, 0.f));
    }

    const int pc_[6] = {0, 0, 0, 1, 1, 2};
    const int pt_[6] = {1, 2, 3, 2, 3, 3};

#pragma unroll
    for (int l = 0; l < 2; l++) {
        const int st = l * 18;
#pragma unroll
        for (int q = 0; q < 4; q++) {
            float a = qp[st + q * 3 + 0];
            float b = qp[st + q * 3 + 1];
            float g = qp[st + q * 3 + 2];
            float sa, ca, sb, cb, sg, cg;
            sincosf(a * 0.5f, &sa, &ca);
            sincosf(b * 0.5f, &sb, &cb);
            sincosf(g * 0.5f, &sg, &cg);
            float2 m00 = make_float2(cb * ca,  sb * sa);
            float2 m01 = make_float2(-sb * ca, -cb * sa);
            float2 m10 = make_float2(sb * ca,  -cb * sa);
            float2 m11 = make_float2(cb * ca,  -sb * sa);
            const float2 em = make_float2(cg, -sg);
            const float2 ep = make_float2(cg,  sg);
            m00 = cmul(em, m00); m01 = cmul(em, m01);
            m10 = cmul(ep, m10); m11 = cmul(ep, m11);
            ap1(s, 8 >> q, m00, m01, m10, m11);
        }
#pragma unroll
        for (int k = 0; k < 6; k++) {
            const float phi = qp[st + 12 + k] * 0.5f;
            float sp, cp;
            sincosf(phi, &sp, &cp);
            const float2 em = make_float2(cp, -sp);
            const float2 ep = make_float2(cp,  sp);
            const int bc = 8 >> pc_[k];
            const int bt = 8 >> pt_[k];
#pragma unroll
            for (int base = 0; base < 16; base++) {
                if (!(base & (bc | bt))) {
                    const int i01 = base | bt, i10 = base | bc, i11 = base | bc | bt;
                    float2 t00 = s[base], t01 = s[i01], t10 = s[i10], t11 = s[i11];
                    s[base] = cmul(em, t00);
                    s[i01]  = cmul(ep, t01);
                    s[i10]  = cmul(em, t11);
                    s[i11]  = cmul(ep, t10);
                }
            }
        }
    }

    float z[4];
#pragma unroll
    for (int w = 0; w < 4; w++) {
        const int bit = 8 >> w;
        float zv = 0.f;
#pragma unroll
        for (int i = 0; i < 16; i++) {
            const float p = s[i].x * s[i].x + s[i].y * s[i].y;
            zv += (i & bit) ? -p : p;
        }
        z[w] = zv;
    }

#pragma unroll
    for (int k = 0; k < 10; k++) {
        float o = pb[k];
#pragma unroll
        for (int j = 0; j < 4; j++) o = fmaf(z[j], pw[k * 4 + j], o);
        out[img * 10 + k] = o;
    }
}

// ---------------------------------------------------------------------------
extern "C" void kernel_launch(void* const* d_in, const int* in_sizes, int n_in,
                              void* d_out, int out_size)
{
    const float* x    = (const float*)d_in[0];
    const float* c1w  = (const float*)d_in[1];
    const float* c1b  = (const float*)d_in[2];
    const float* c2w  = (const float*)d_in[3];
    const float* c2b  = (const float*)d_in[4];
    const float* dw   = (const float*)d_in[5];
    const float* db   = (const float*)d_in[6];
    const float* qp   = (const float*)d_in[7];
    const float* pw   = (const float*)d_in[8];
    const float* pb   = (const float*)d_in[9];
    float* out = (float*)d_out;

    int B = in_sizes[0] / 784;
    if (B > B_MAX) B = B_MAX;

    k1_conv1<<<B, 196>>>(x, c1w, c1b);
    k2_conv2_dense<<<B, 224>>>(c2w, c2b, dw, db);
    k3_quantum_post<<<(B + 127) / 128, 128>>>(qp, pw, pb, out, B);
}